// round 12
// baseline (speedup 1.0000x reference)
#include <cuda_runtime.h>
#include <math.h>

#define C_IN 768
#define DDIM 8
#define LDIM 8

#define THREADS 256
#define TILE 128                // tokens per block (quad handles 2 tokens)
#define HALF 64                 // tokens per "slot" (t1 = t0 + HALF)
#define NITER (C_IN / 16)       // 48 chunks, 4 floats per lane per chunk
#define EXP_THREADS 192         // phase-2 channel owners (192*4 = 768)

// Scratch (no allocations allowed)
__device__ float g_partials[2048];
__device__ unsigned int g_done = 0;   // self-resetting via atomicInc wrap

static __device__ __forceinline__ unsigned long long pack2(float lo, float hi) {
    unsigned long long r;
    asm("mov.b64 %0, {%1, %2};" : "=l"(r) : "f"(lo), "f"(hi));
    return r;
}
static __device__ __forceinline__ void unpack2(unsigned long long v, float& lo, float& hi) {
    asm("mov.b64 {%0, %1}, %2;" : "=f"(lo), "=f"(hi) : "l"(v));
}
// Packed fp32x2 FMA (sm_100+): 2 IEEE fp32 FMAs per instruction.
static __device__ __forceinline__ unsigned long long fma2(unsigned long long a,
                                                          unsigned long long b,
                                                          unsigned long long c) {
    unsigned long long d;
    asm("fma.rn.f32x2 %0, %1, %2, %3;" : "=l"(d) : "l"(a), "l"(b), "l"(c));
    return d;
}

// Fused kernel:
//   Phase 1: compress GEMV, 4 lanes/token but each quad drives 2 tokens so
//            every weight LDS.128 feeds 4 fma2 (halved L1 weight traffic).
//            Depth-2 register prefetch of z, barrier-free. Gumbel argmax;
//            codes -> shared, error partial -> global.
//   Phase 2: expand z_q = codes @ We + be from shared, coalesced STG.128.
//   Tail:    deterministic last-block reduction of error partials.
__global__ void __launch_bounds__(THREADS) k_fused(
    const float* __restrict__ z, const float* __restrict__ u,
    const float* __restrict__ Wc, const float* __restrict__ bc,
    const float* __restrict__ We, const float* __restrict__ be,
    const float* __restrict__ cb,
    float* __restrict__ out, int ntok, int nblk,
    long long erridx, float errinv)
{
    __shared__ __align__(16) float sWcT[DDIM * C_IN];            // 24 KB transposed
    __shared__ __align__(16) unsigned long long sC[TILE * DDIM]; // 8 KB (code,code)
    __shared__ float sBC[DDIM];
    __shared__ float sCB[DDIM * LDIM];
    __shared__ float sRed[THREADS / 32];
    __shared__ unsigned int sLast;

    const int tid = threadIdx.x;

    // Stage transposed compress weights (coalesced global reads)
    for (int i = tid; i < C_IN * DDIM; i += THREADS) {
        int c = i >> 3, d = i & 7;
        sWcT[d * C_IN + c] = Wc[i];
    }
    if (tid < DDIM) sBC[tid] = bc[tid];
    if (tid < DDIM * LDIM) sCB[tid] = cb[tid];
    __syncthreads();

    // ---------------- Phase 1: compress (2 tokens per quad) ----------------
    const int j = tid & 3;                         // lane within quad
    const int trow = tid >> 2;                     // 0..63
    const int tokA = blockIdx.x * TILE + trow;     // first token
    const int tokB = tokA + HALF;                  // second token
    const int lA = (tokA < ntok) ? tokA : (ntok - 1);
    const int lB = (tokB < ntok) ? tokB : (ntok - 1);
    const float* zrowA = z + (size_t)lA * C_IN + 4 * j;
    const float* zrowB = z + (size_t)lB * C_IN + 4 * j;

    unsigned long long accA[DDIM], accB[DDIM];
    #pragma unroll
    for (int d = 0; d < DDIM; d++) { accA[d] = pack2(0.f, 0.f); accB[d] = accA[d]; }

    // Depth-2 software pipeline over chunks
    float4 a0 = *reinterpret_cast<const float4*>(zrowA);
    float4 b0 = *reinterpret_cast<const float4*>(zrowB);
    float4 a1 = *reinterpret_cast<const float4*>(zrowA + 16);
    float4 b1 = *reinterpret_cast<const float4*>(zrowB + 16);

    #pragma unroll 2
    for (int k = 0; k < NITER; k += 2) {
        float4 na0, nb0, na1, nb1;
        if (k + 2 < NITER) {
            na0 = *reinterpret_cast<const float4*>(zrowA + 16 * (k + 2));
            nb0 = *reinterpret_cast<const float4*>(zrowB + 16 * (k + 2));
            na1 = *reinterpret_cast<const float4*>(zrowA + 16 * (k + 3));
            nb1 = *reinterpret_cast<const float4*>(zrowB + 16 * (k + 3));
        }
        // chunk k
        {
            unsigned long long zpa01 = pack2(a0.x, a0.y);
            unsigned long long zpa23 = pack2(a0.z, a0.w);
            unsigned long long zpb01 = pack2(b0.x, b0.y);
            unsigned long long zpb23 = pack2(b0.z, b0.w);
            const float* wbase = sWcT + 16 * k + 4 * j;
            #pragma unroll
            for (int d = 0; d < DDIM; d++) {
                ulonglong2 wd =
                    *reinterpret_cast<const ulonglong2*>(wbase + d * C_IN);
                accA[d] = fma2(zpa01, wd.x, accA[d]);
                accA[d] = fma2(zpa23, wd.y, accA[d]);
                accB[d] = fma2(zpb01, wd.x, accB[d]);
                accB[d] = fma2(zpb23, wd.y, accB[d]);
            }
        }
        // chunk k+1
        {
            unsigned long long zpa01 = pack2(a1.x, a1.y);
            unsigned long long zpa23 = pack2(a1.z, a1.w);
            unsigned long long zpb01 = pack2(b1.x, b1.y);
            unsigned long long zpb23 = pack2(b1.z, b1.w);
            const float* wbase = sWcT + 16 * (k + 1) + 4 * j;
            #pragma unroll
            for (int d = 0; d < DDIM; d++) {
                ulonglong2 wd =
                    *reinterpret_cast<const ulonglong2*>(wbase + d * C_IN);
                accA[d] = fma2(zpa01, wd.x, accA[d]);
                accA[d] = fma2(zpa23, wd.y, accA[d]);
                accB[d] = fma2(zpb01, wd.x, accB[d]);
                accB[d] = fma2(zpb23, wd.y, accB[d]);
            }
        }
        a0 = na0; b0 = nb0; a1 = na1; b1 = nb1;
    }

    // Quad reduction; lane j keeps dims 2j, 2j+1 for both tokens
    const int d0 = 2 * j, d1 = 2 * j + 1;
    float zcA0 = 0.f, zcA1 = 0.f, zcB0 = 0.f, zcB1 = 0.f;
    #pragma unroll
    for (int d = 0; d < DDIM; d++) {
        float lo, hi, va, vb;
        unpack2(accA[d], lo, hi); va = lo + hi;
        unpack2(accB[d], lo, hi); vb = lo + hi;
        va += __shfl_xor_sync(0xffffffffu, va, 1);
        va += __shfl_xor_sync(0xffffffffu, va, 2);
        vb += __shfl_xor_sync(0xffffffffu, vb, 1);
        vb += __shfl_xor_sync(0xffffffffu, vb, 2);
        float bcv = sBC[d];
        va += bcv; vb += bcv;
        if (d == d0) { zcA0 = va; zcB0 = vb; }
        if (d == d1) { zcA1 = va; zcB1 = vb; }
    }

    // Argmax per token (sequential to bound register pressure)
    float err = 0.0f;
    const float cb00 = sCB[d0 * LDIM + 0];  // codebook rows identical per-dim
    #pragma unroll
    for (int half = 0; half < 2; half++) {
        const int mtok = half ? tokB : tokA;
        const int lt   = half ? lB : lA;
        const float zv0 = half ? zcB0 : zcA0;
        const float zv1 = half ? zcB1 : zcA1;
        const float4* u4 = reinterpret_cast<const float4*>(
            u + (size_t)lt * (DDIM * LDIM) + 16 * j);
        float4 ua = u4[0], ub = u4[1], uc = u4[2], ud = u4[3];
        float uv0[LDIM] = {ua.x, ua.y, ua.z, ua.w, ub.x, ub.y, ub.z, ub.w};
        float uv1[LDIM] = {uc.x, uc.y, uc.z, uc.w, ud.x, ud.y, ud.z, ud.w};

        // argmax_l of gumbel(u) - |zc - cb| (== reference softmax argmax,
        // TAU=1; strict > keeps first index on ties, matching jnp.argmax)
        float best0 = -INFINITY, best1 = -INFINITY;
        float code0 = 0.f, code1 = 0.f;
        #pragma unroll
        for (int l = 0; l < LDIM; l++) {
            float cbv0 = sCB[d0 * LDIM + l];
            float cbv1 = sCB[d1 * LDIM + l];
            float g0 = -logf(-logf(uv0[l] + 1e-10f));
            float g1 = -logf(-logf(uv1[l] + 1e-10f));
            float s0 = g0 - fabsf(zv0 - cbv0);
            float s1 = g1 - fabsf(zv1 - cbv1);
            if (s0 > best0) { best0 = s0; code0 = cbv0; }
            if (s1 > best1) { best1 = s1; code1 = cbv1; }
        }
        if (mtok < ntok) {
            float e0 = zv0 - code0, e1 = zv1 - code1;
            err += e0 * e0 + e1 * e1;
        }
        ulonglong2 cw;
        cw.x = pack2(code0, code0);
        cw.y = pack2(code1, code1);
        *reinterpret_cast<ulonglong2*>(
            &sC[(trow + half * HALF) * DDIM + d0]) = cw;
    }
    (void)cb00;

    // Block-reduce squared error -> per-block partial
    #pragma unroll
    for (int o = 16; o > 0; o >>= 1) err += __shfl_down_sync(0xffffffffu, err, o);
    if ((tid & 31) == 0) sRed[tid >> 5] = err;
    __syncthreads();   // also publishes sC for phase 2
    if (tid == 0) {
        float t = 0.f;
        #pragma unroll
        for (int w = 0; w < THREADS / 32; w++) t += sRed[w];
        g_partials[blockIdx.x] = t;
    }

    // ---------------- Phase 2: expand ----------------
    if (tid < EXP_THREADS) {
        const int c0 = tid * 4;
        ulonglong2 wv[DDIM];
        #pragma unroll
        for (int d = 0; d < DDIM; d++)
            wv[d] = *reinterpret_cast<const ulonglong2*>(&We[d * C_IN + c0]);
        ulonglong2 bev = *reinterpret_cast<const ulonglong2*>(&be[c0]);

        const int tok0 = blockIdx.x * TILE;
        int tmax = ntok - tok0;
        if (tmax > TILE) tmax = TILE;

        int t = 0;
        for (; t + 4 <= tmax; t += 4) {
            unsigned long long a[4][2];
            #pragma unroll
            for (int q = 0; q < 4; q++) { a[q][0] = bev.x; a[q][1] = bev.y; }
            #pragma unroll
            for (int d = 0; d < DDIM; d++) {
                #pragma unroll
                for (int q = 0; q < 4; q++) {
                    unsigned long long cd = sC[(t + q) * DDIM + d];  // broadcast
                    a[q][0] = fma2(cd, wv[d].x, a[q][0]);
                    a[q][1] = fma2(cd, wv[d].y, a[q][1]);
                }
            }
            #pragma unroll
            for (int q = 0; q < 4; q++) {
                float4 o;
                unpack2(a[q][0], o.x, o.y);
                unpack2(a[q][1], o.z, o.w);
                *reinterpret_cast<float4*>(
                    &out[(size_t)(tok0 + t + q) * C_IN + c0]) = o;
            }
        }
        for (; t < tmax; t++) {
            unsigned long long s0 = bev.x, s1 = bev.y;
            #pragma unroll
            for (int d = 0; d < DDIM; d++) {
                unsigned long long cd = sC[t * DDIM + d];
                s0 = fma2(cd, wv[d].x, s0);
                s1 = fma2(cd, wv[d].y, s1);
            }
            float4 o;
            unpack2(s0, o.x, o.y);
            unpack2(s1, o.z, o.w);
            *reinterpret_cast<float4*>(&out[(size_t)(tok0 + t) * C_IN + c0]) = o;
        }
    }

    // ---------------- Tail: last block finalizes the error scalar ----------
    if (erridx >= 0) {
        if (tid == 0) {
            __threadfence();  // publish g_partials[bid] before counting
            // wraps to 0 after nblk increments -> self-resetting across replays
            sLast = (atomicInc(&g_done, (unsigned)nblk - 1u) == (unsigned)nblk - 1u);
        }
        __syncthreads();
        if (sLast) {
            float s = 0.f;
            for (int i = tid; i < nblk; i += THREADS) s += g_partials[i];
            #pragma unroll
            for (int o = 16; o > 0; o >>= 1)
                s += __shfl_down_sync(0xffffffffu, s, o);
            if ((tid & 31) == 0) sRed[tid >> 5] = s;
            __syncthreads();
            if (tid == 0) {
                float tot = 0.f;
                #pragma unroll
                for (int w = 0; w < THREADS / 32; w++) tot += sRed[w];
                out[erridx] = tot * errinv;
            }
        }
    }
}

extern "C" void kernel_launch(void* const* d_in, const int* in_sizes, int n_in,
                              void* d_out, int out_size) {
    const float* z  = (const float*)d_in[0];
    const float* u  = (const float*)d_in[1];
    const float* Wc = (const float*)d_in[2];
    const float* bc = (const float*)d_in[3];
    const float* We = (const float*)d_in[4];
    const float* be = (const float*)d_in[5];
    const float* cb = (const float*)d_in[6];
    // d_in[7] = codebook_mask: all-true here (levels == [8]*8), intentionally unused.
    float* out = (float*)d_out;

    const int ntok = in_sizes[0] / C_IN;            // 65536
    const int nblk = (ntok + TILE - 1) / TILE;      // 512

    long long erridx = (out_size > ntok * C_IN) ? (long long)ntok * C_IN : -1;

    k_fused<<<nblk, THREADS>>>(z, u, Wc, bc, We, be, cb, out, ntok, nblk,
                               erridx, 1.0f / ((float)ntok * (float)DDIM));
}

// round 13
// speedup vs baseline: 1.2395x; 1.2395x over previous
#include <cuda_runtime.h>
#include <math.h>

#define C_IN 768
#define DDIM 8
#define LDIM 8

#define THREADS 256
#define TILE 128                // tokens per block (quad handles 2 tokens)
#define HALF 64                 // t1 = t0 + HALF
#define NITER (C_IN / 16)       // 48 chunks, 4 floats per lane per chunk
#define EXP_THREADS 192         // phase-2 channel owners (192*4 = 768)

// Scratch (no allocations allowed)
__device__ float g_partials[2048];
__device__ unsigned int g_done = 0;   // self-resetting via atomicInc wrap

static __device__ __forceinline__ unsigned long long pack2(float lo, float hi) {
    unsigned long long r;
    asm("mov.b64 %0, {%1, %2};" : "=l"(r) : "f"(lo), "f"(hi));
    return r;
}
static __device__ __forceinline__ void unpack2(unsigned long long v, float& lo, float& hi) {
    asm("mov.b64 {%0, %1}, %2;" : "=f"(lo), "=f"(hi) : "l"(v));
}
// Packed fp32x2 FMA (sm_100+): 2 IEEE fp32 FMAs per instruction.
static __device__ __forceinline__ unsigned long long fma2(unsigned long long a,
                                                          unsigned long long b,
                                                          unsigned long long c) {
    unsigned long long d;
    asm("fma.rn.f32x2 %0, %1, %2, %3;" : "=l"(d) : "l"(a), "l"(b), "l"(c));
    return d;
}

// Fused kernel:
//   Phase 1: compress GEMV, 4 lanes/token, each quad drives 2 tokens so every
//            weight LDS.128 feeds 4 fma2 (halved L1 weight traffic). Simple
//            unroll-4 mainloop (ptxas batches the LDGs); no explicit prefetch
//            registers -> live set fits the 64-reg / 4-blocks-per-SM cap ->
//            grid 512 runs in a SINGLE wave. Gumbel argmax; codes -> shared.
//   Phase 2: expand z_q = codes @ We + be from shared, coalesced STG.128.
//   Tail:    deterministic last-block reduction of error partials.
__global__ void __launch_bounds__(THREADS, 4) k_fused(
    const float* __restrict__ z, const float* __restrict__ u,
    const float* __restrict__ Wc, const float* __restrict__ bc,
    const float* __restrict__ We, const float* __restrict__ be,
    const float* __restrict__ cb,
    float* __restrict__ out, int ntok, int nblk,
    long long erridx, float errinv)
{
    __shared__ __align__(16) float sWcT[DDIM * C_IN];            // 24 KB transposed
    __shared__ __align__(16) unsigned long long sC[TILE * DDIM]; // 8 KB (code,code)
    __shared__ float sBC[DDIM];
    __shared__ float sCB[DDIM * LDIM];
    __shared__ float sRed[THREADS / 32];
    __shared__ unsigned int sLast;

    const int tid = threadIdx.x;

    // Stage transposed compress weights (coalesced global reads)
    for (int i = tid; i < C_IN * DDIM; i += THREADS) {
        int c = i >> 3, d = i & 7;
        sWcT[d * C_IN + c] = Wc[i];
    }
    if (tid < DDIM) sBC[tid] = bc[tid];
    if (tid < DDIM * LDIM) sCB[tid] = cb[tid];
    __syncthreads();

    // ---------------- Phase 1: compress (2 tokens per quad) ----------------
    const int j = tid & 3;                         // lane within quad
    const int trow = tid >> 2;                     // 0..63
    const int tokA = blockIdx.x * TILE + trow;     // first token
    const int tokB = tokA + HALF;                  // second token
    const int lA = (tokA < ntok) ? tokA : (ntok - 1);
    const int lB = (tokB < ntok) ? tokB : (ntok - 1);
    const float* zrowA = z + (size_t)lA * C_IN + 4 * j;
    const float* zrowB = z + (size_t)lB * C_IN + 4 * j;

    unsigned long long accA[DDIM], accB[DDIM];
    #pragma unroll
    for (int d = 0; d < DDIM; d++) { accA[d] = pack2(0.f, 0.f); accB[d] = accA[d]; }

    // Simple mainloop; unroll-4 lets ptxas front-batch the LDG.128s (MLP~8)
    #pragma unroll 4
    for (int k = 0; k < NITER; k++) {
        float4 av = *reinterpret_cast<const float4*>(zrowA + 16 * k);
        float4 bv = *reinterpret_cast<const float4*>(zrowB + 16 * k);
        unsigned long long zpa01 = pack2(av.x, av.y);
        unsigned long long zpa23 = pack2(av.z, av.w);
        unsigned long long zpb01 = pack2(bv.x, bv.y);
        unsigned long long zpb23 = pack2(bv.z, bv.w);
        const float* wbase = sWcT + 16 * k + 4 * j;
        #pragma unroll
        for (int d = 0; d < DDIM; d++) {
            ulonglong2 wd = *reinterpret_cast<const ulonglong2*>(wbase + d * C_IN);
            accA[d] = fma2(zpa01, wd.x, accA[d]);
            accA[d] = fma2(zpa23, wd.y, accA[d]);
            accB[d] = fma2(zpb01, wd.x, accB[d]);
            accB[d] = fma2(zpb23, wd.y, accB[d]);
        }
    }

    // Quad reduction; lane j keeps dims 2j, 2j+1 for both tokens
    const int d0 = 2 * j, d1 = 2 * j + 1;
    float zcA0 = 0.f, zcA1 = 0.f, zcB0 = 0.f, zcB1 = 0.f;
    #pragma unroll
    for (int d = 0; d < DDIM; d++) {
        float lo, hi, va, vb;
        unpack2(accA[d], lo, hi); va = lo + hi;
        unpack2(accB[d], lo, hi); vb = lo + hi;
        va += __shfl_xor_sync(0xffffffffu, va, 1);
        va += __shfl_xor_sync(0xffffffffu, va, 2);
        vb += __shfl_xor_sync(0xffffffffu, vb, 1);
        vb += __shfl_xor_sync(0xffffffffu, vb, 2);
        float bcv = sBC[d];
        va += bcv; vb += bcv;
        if (d == d0) { zcA0 = va; zcB0 = vb; }
        if (d == d1) { zcA1 = va; zcB1 = vb; }
    }

    // Argmax per token (sequential halves bound register pressure)
    float err = 0.0f;
    #pragma unroll
    for (int half = 0; half < 2; half++) {
        const int mtok = half ? tokB : tokA;
        const int lt   = half ? lB : lA;
        const float zv0 = half ? zcB0 : zcA0;
        const float zv1 = half ? zcB1 : zcA1;
        const float4* u4 = reinterpret_cast<const float4*>(
            u + (size_t)lt * (DDIM * LDIM) + 16 * j);
        float4 ua = u4[0], ub = u4[1], uc = u4[2], ud = u4[3];
        float uv0[LDIM] = {ua.x, ua.y, ua.z, ua.w, ub.x, ub.y, ub.z, ub.w};
        float uv1[LDIM] = {uc.x, uc.y, uc.z, uc.w, ud.x, ud.y, ud.z, ud.w};

        // argmax_l of gumbel(u) - |zc - cb| (== reference softmax argmax,
        // TAU=1; strict > keeps first index on ties, matching jnp.argmax)
        float best0 = -INFINITY, best1 = -INFINITY;
        float code0 = 0.f, code1 = 0.f;
        #pragma unroll
        for (int l = 0; l < LDIM; l++) {
            float cbv0 = sCB[d0 * LDIM + l];
            float cbv1 = sCB[d1 * LDIM + l];
            float g0 = -logf(-logf(uv0[l] + 1e-10f));
            float g1 = -logf(-logf(uv1[l] + 1e-10f));
            float s0 = g0 - fabsf(zv0 - cbv0);
            float s1 = g1 - fabsf(zv1 - cbv1);
            if (s0 > best0) { best0 = s0; code0 = cbv0; }
            if (s1 > best1) { best1 = s1; code1 = cbv1; }
        }
        if (mtok < ntok) {
            float e0 = zv0 - code0, e1 = zv1 - code1;
            err += e0 * e0 + e1 * e1;
        }
        ulonglong2 cw;
        cw.x = pack2(code0, code0);
        cw.y = pack2(code1, code1);
        *reinterpret_cast<ulonglong2*>(
            &sC[(trow + half * HALF) * DDIM + d0]) = cw;
    }

    // Block-reduce squared error -> per-block partial
    #pragma unroll
    for (int o = 16; o > 0; o >>= 1) err += __shfl_down_sync(0xffffffffu, err, o);
    if ((tid & 31) == 0) sRed[tid >> 5] = err;
    __syncthreads();   // also publishes sC for phase 2
    if (tid == 0) {
        float t = 0.f;
        #pragma unroll
        for (int w = 0; w < THREADS / 32; w++) t += sRed[w];
        g_partials[blockIdx.x] = t;
    }

    // ---------------- Phase 2: expand ----------------
    if (tid < EXP_THREADS) {
        const int c0 = tid * 4;
        ulonglong2 wv[DDIM];
        #pragma unroll
        for (int d = 0; d < DDIM; d++)
            wv[d] = *reinterpret_cast<const ulonglong2*>(&We[d * C_IN + c0]);
        ulonglong2 bev = *reinterpret_cast<const ulonglong2*>(&be[c0]);

        const int tok0 = blockIdx.x * TILE;
        int tmax = ntok - tok0;
        if (tmax > TILE) tmax = TILE;

        int t = 0;
        for (; t + 4 <= tmax; t += 4) {
            unsigned long long a[4][2];
            #pragma unroll
            for (int q = 0; q < 4; q++) { a[q][0] = bev.x; a[q][1] = bev.y; }
            #pragma unroll
            for (int d = 0; d < DDIM; d++) {
                #pragma unroll
                for (int q = 0; q < 4; q++) {
                    unsigned long long cd = sC[(t + q) * DDIM + d];  // broadcast
                    a[q][0] = fma2(cd, wv[d].x, a[q][0]);
                    a[q][1] = fma2(cd, wv[d].y, a[q][1]);
                }
            }
            #pragma unroll
            for (int q = 0; q < 4; q++) {
                float4 o;
                unpack2(a[q][0], o.x, o.y);
                unpack2(a[q][1], o.z, o.w);
                *reinterpret_cast<float4*>(
                    &out[(size_t)(tok0 + t + q) * C_IN + c0]) = o;
            }
        }
        for (; t < tmax; t++) {
            unsigned long long s0 = bev.x, s1 = bev.y;
            #pragma unroll
            for (int d = 0; d < DDIM; d++) {
                unsigned long long cd = sC[t * DDIM + d];
                s0 = fma2(cd, wv[d].x, s0);
                s1 = fma2(cd, wv[d].y, s1);
            }
            float4 o;
            unpack2(s0, o.x, o.y);
            unpack2(s1, o.z, o.w);
            *reinterpret_cast<float4*>(&out[(size_t)(tok0 + t) * C_IN + c0]) = o;
        }
    }

    // ---------------- Tail: last block finalizes the error scalar ----------
    if (erridx >= 0) {
        if (tid == 0) {
            __threadfence();  // publish g_partials[bid] before counting
            // wraps to 0 after nblk increments -> self-resetting across replays
            sLast = (atomicInc(&g_done, (unsigned)nblk - 1u) == (unsigned)nblk - 1u);
        }
        __syncthreads();
        if (sLast) {
            float s = 0.f;
            for (int i = tid; i < nblk; i += THREADS) s += g_partials[i];
            #pragma unroll
            for (int o = 16; o > 0; o >>= 1)
                s += __shfl_down_sync(0xffffffffu, s, o);
            if ((tid & 31) == 0) sRed[tid >> 5] = s;
            __syncthreads();
            if (tid == 0) {
                float tot = 0.f;
                #pragma unroll
                for (int w = 0; w < THREADS / 32; w++) tot += sRed[w];
                out[erridx] = tot * errinv;
            }
        }
    }
}

extern "C" void kernel_launch(void* const* d_in, const int* in_sizes, int n_in,
                              void* d_out, int out_size) {
    const float* z  = (const float*)d_in[0];
    const float* u  = (const float*)d_in[1];
    const float* Wc = (const float*)d_in[2];
    const float* bc = (const float*)d_in[3];
    const float* We = (const float*)d_in[4];
    const float* be = (const float*)d_in[5];
    const float* cb = (const float*)d_in[6];
    // d_in[7] = codebook_mask: all-true here (levels == [8]*8), intentionally unused.
    float* out = (float*)d_out;

    const int ntok = in_sizes[0] / C_IN;            // 65536
    const int nblk = (ntok + TILE - 1) / TILE;      // 512

    long long erridx = (out_size > ntok * C_IN) ? (long long)ntok * C_IN : -1;

    k_fused<<<nblk, THREADS>>>(z, u, Wc, bc, We, be, cb, out, ntok, nblk,
                               erridx, 1.0f / ((float)ntok * (float)DDIM));
}